// round 11
// baseline (speedup 1.0000x reference)
#include <cuda_runtime.h>

// Problem constants
#define B_    16
#define CIN   512
#define N_    1024
#define HEADS_ 4
#define DH_   32
#define DV_   128
#define OTOT  768     // 128 (q) + 128 (k) + 512 (v) output channels

typedef unsigned long long ull;

// ---------------- f32x2 packed helpers (sm_103a FFMA2 path) ----------------
__device__ __forceinline__ ull f2pk(float lo, float hi) {
    ull r; asm("mov.b64 %0, {%1, %2};" : "=l"(r) : "f"(lo), "f"(hi)); return r;
}
__device__ __forceinline__ ull f2dup(float x) {
    ull r; asm("mov.b64 %0, {%1, %1};" : "=l"(r) : "f"(x)); return r;
}
__device__ __forceinline__ void f2upk(ull v, float& lo, float& hi) {
    asm("mov.b64 {%0, %1}, %2;" : "=f"(lo), "=f"(hi) : "l"(v));
}
__device__ __forceinline__ ull f2fma(ull a, ull b, ull c) {
    ull d; asm("fma.rn.f32x2 %0, %1, %2, %3;" : "=l"(d) : "l"(a), "l"(b), "l"(c)); return d;
}
__device__ __forceinline__ ull f2mul(ull a, ull b) {
    ull d; asm("mul.rn.f32x2 %0, %1, %2;" : "=l"(d) : "l"(a), "l"(b)); return d;
}

// ---------------- scratch (device globals; no allocation allowed) ----------
__device__ float g_Weff[OTOT * CIN];       // folded conv+BN weights
__device__ float g_beff[OTOT];             // folded bias
__device__ float g_q[B_ * 128 * N_];       // [b][h*32+d][n]
__device__ float g_k[B_ * 128 * N_];       // [b][h*32+d][n]
__device__ float g_v[B_ * 512 * N_];       // [b][h*128+c][n]
__device__ float g_pos[HEADS_ * DH_ * N_]; // [h][d][n]

// ---------------- kernel 1: fold BN into conv weights ----------------------
__global__ void fold_kernel(
    const float* __restrict__ Wq, const float* __restrict__ bq,
    const float* __restrict__ qg, const float* __restrict__ qb,
    const float* __restrict__ qm, const float* __restrict__ qv,
    const float* __restrict__ Wk, const float* __restrict__ bk,
    const float* __restrict__ kg, const float* __restrict__ kb,
    const float* __restrict__ km, const float* __restrict__ kv,
    const float* __restrict__ Wv, const float* __restrict__ bv,
    const float* __restrict__ vg, const float* __restrict__ vb,
    const float* __restrict__ vm, const float* __restrict__ vv)
{
    int idx = blockIdx.x * blockDim.x + threadIdx.x;
    if (idx >= OTOT * CIN) return;
    int o = idx >> 9;
    int c = idx & 511;
    const float *W, *bb, *g, *be, *mu, *va;
    int ol;
    if (o < 128)      { W = Wq; bb = bq; g = qg; be = qb; mu = qm; va = qv; ol = o; }
    else if (o < 256) { W = Wk; bb = bk; g = kg; be = kb; mu = km; va = kv; ol = o - 128; }
    else              { W = Wv; bb = bv; g = vg; be = vb; mu = vm; va = vv; ol = o - 256; }
    float s = g[ol] * rsqrtf(va[ol] + 1e-5f);
    g_Weff[idx] = W[ol * CIN + c] * s;
    if (c == 0) g_beff[o] = (bb[ol] - mu[ol]) * s + be[ol];
}

// ---------------- kernel 2: pos = rel_h + rel_w, [h][d][n] -----------------
__global__ void pos_kernel(const float* __restrict__ rel_h,
                           const float* __restrict__ rel_w)
{
    int idx = blockIdx.x * blockDim.x + threadIdx.x;  // HEADS*DH*N = 131072
    if (idx >= HEADS_ * DH_ * N_) return;
    int n  = idx & (N_ - 1);
    int hd = idx >> 10;            // h*32 + d
    int w  = n >> 5;
    int hh = n & 31;
    g_pos[idx] = rel_h[hd * 32 + hh] + rel_w[hd * 32 + w];
}

// ---------------- kernel 3: fused QKV GEMM  Y[768,1024] = Weff @ x_b -------
// Tile: BM=64, BN=64, BK=16; 256 threads; rows 4*ty+i, cols 4*tx+{0..3}.
__global__ __launch_bounds__(256) void qkv_gemm(const float* __restrict__ x)
{
    __shared__ __align__(16) float As[16][68];   // As[kk][m]  (A transposed)
    __shared__ __align__(16) float Bs[16][68];   // Bs[kk][n]

    int b  = blockIdx.z;
    int m0 = blockIdx.y * 64;
    int n0 = blockIdx.x * 64;
    int tid = threadIdx.x;
    int ty = tid >> 4, tx = tid & 15;
    const float* xb = x + (size_t)b * CIN * N_;

    ull acc[4][2];
#pragma unroll
    for (int i = 0; i < 4; i++) { acc[i][0] = 0ull; acc[i][1] = 0ull; }

    for (int k0 = 0; k0 < CIN; k0 += 16) {
        // load A tile 64x16 (one float4 per thread), transpose into smem
        {
            int row = tid >> 2;            // 0..63
            int cg  = (tid & 3) * 4;       // 0,4,8,12
            float4 av = *(const float4*)(g_Weff + (m0 + row) * CIN + k0 + cg);
            As[cg + 0][row] = av.x;
            As[cg + 1][row] = av.y;
            As[cg + 2][row] = av.z;
            As[cg + 3][row] = av.w;
        }
        // load B tile 16x64 (4 floats per thread, coalesced 64-float runs)
        {
            int nn = tid & 63;
            int kk = tid >> 6;             // 0..3
#pragma unroll
            for (int it = 0; it < 4; it++)
                Bs[kk + it * 4][nn] = xb[(size_t)(k0 + kk + it * 4) * N_ + n0 + nn];
        }
        __syncthreads();
#pragma unroll
        for (int kk = 0; kk < 16; kk++) {
            float4 a4 = *(const float4*)(&As[kk][4 * ty]);     // LDS.128 bcast
            ull ad0 = f2dup(a4.x), ad1 = f2dup(a4.y), ad2 = f2dup(a4.z), ad3 = f2dup(a4.w);
            float4 b4 = *(const float4*)(&Bs[kk][4 * tx]);     // LDS.128
            ull b01 = f2pk(b4.x, b4.y);
            ull b23 = f2pk(b4.z, b4.w);
            acc[0][0] = f2fma(ad0, b01, acc[0][0]);
            acc[0][1] = f2fma(ad0, b23, acc[0][1]);
            acc[1][0] = f2fma(ad1, b01, acc[1][0]);
            acc[1][1] = f2fma(ad1, b23, acc[1][1]);
            acc[2][0] = f2fma(ad2, b01, acc[2][0]);
            acc[2][1] = f2fma(ad2, b23, acc[2][1]);
            acc[3][0] = f2fma(ad3, b01, acc[3][0]);
            acc[3][1] = f2fma(ad3, b23, acc[3][1]);
        }
        __syncthreads();
    }

    // epilogue: scatter into q / k / v layouts with bias (STG.128)
#pragma unroll
    for (int i = 0; i < 4; i++) {
        int o = m0 + 4 * ty + i;
        float bias = g_beff[o];
        float* dst;
        if (o < 128)      dst = g_q + (size_t)(b * 128 + o) * N_;
        else if (o < 256) dst = g_k + (size_t)(b * 128 + (o - 128)) * N_;
        else              dst = g_v + (size_t)(b * 512 + (o - 256)) * N_;
        float c0, c1, c2, c3;
        f2upk(acc[i][0], c0, c1);
        f2upk(acc[i][1], c2, c3);
        float4 w; w.x = c0 + bias; w.y = c1 + bias; w.z = c2 + bias; w.w = c3 + bias;
        *reinterpret_cast<float4*>(dst + n0 + 4 * tx) = w;
    }
}

// ---------------- kernel 4: fused flash attention + residual ---------------
// Per CTA: one (b, h) and 64 query rows.  d'=64 (q||pos vs k||q), dv=128.
// Smem: Qs[64][68], Ks[64][68], Vs[64][132] — all rows 16B-aligned for LDS.128.
// P stays in registers; GEMM2 fetches p[s][row] via __shfl from the lane that
// owns column s (src = halfbase | s>>2, reg s&3).  67 KB smem -> 3 CTAs/SM.
#define QP 68
#define VP 132
#define ATTN_SMEM_FLOATS (2 * 64 * QP + 64 * VP)
#define ATTN_SMEM_BYTES  (ATTN_SMEM_FLOATS * 4)

__global__ __launch_bounds__(256, 3) void attn_kernel(const float* __restrict__ x,
                                                      float* __restrict__ out)
{
    extern __shared__ __align__(16) float sm[];
    float* Qs = sm;                 // Qs[d*QP + r]
    float* Ks = sm + 64 * QP;       // Ks[d*QP + s]
    float* Vs = sm + 2 * 64 * QP;   // Vs[s*VP + c]

    int n0 = blockIdx.x * 64;
    int h  = blockIdx.y;
    int b  = blockIdx.z;
    int tid = threadIdx.x;
    int ty = tid >> 4, tx = tid & 15;
    int halfbase = tid & 16;        // lane-half base within the warp (same ty group)

    const float* qbh  = g_q + (size_t)(b * 128 + h * 32) * N_;   // [d][n]
    const float* kbh  = g_k + (size_t)(b * 128 + h * 32) * N_;
    const float* vbh  = g_v + (size_t)(b * 512 + h * 128) * N_;  // [c][n]
    const float* posh = g_pos + (size_t)h * 32 * N_;

    // fill Q' (q rows then pos rows), transposed: Qs[d][r]
    for (int idx = tid; idx < 64 * 64; idx += 256) {
        int r = idx & 63, d = idx >> 6;
        Qs[d * QP + r] = (d < 32) ? qbh[(size_t)d * N_ + n0 + r]
                                  : posh[(size_t)(d - 32) * N_ + n0 + r];
    }

    float m[4], l[4];
    ull O2[4][4];
#pragma unroll
    for (int i = 0; i < 4; i++) {
        m[i] = -1e30f; l[i] = 0.f;
#pragma unroll
        for (int j = 0; j < 4; j++) O2[i][j] = 0ull;
    }
    __syncthreads();

    for (int s0 = 0; s0 < N_; s0 += 64) {
        // fill K' = [k ; q] (transposed) and V (transposed: Vs[s][c], c-pairs)
        for (int idx = tid; idx < 64 * 64; idx += 256) {
            int s = idx & 63, d = idx >> 6;
            Ks[d * QP + s] = (d < 32) ? kbh[(size_t)d * N_ + s0 + s]
                                      : qbh[(size_t)(d - 32) * N_ + s0 + s];
        }
        for (int idx = tid; idx < 64 * 64; idx += 256) {
            int s = idx & 63, cp = idx >> 6;   // cp = column pair 0..63
            float2 w;
            w.x = vbh[(size_t)(2 * cp) * N_ + s0 + s];
            w.y = vbh[(size_t)(2 * cp + 1) * N_ + s0 + s];
            *reinterpret_cast<float2*>(Vs + s * VP + 2 * cp) = w;
        }
        __syncthreads();

        // GEMM1: S[64r x 64s] over d'=64; rows 4ty+i, cols 4tx+{0..3}
        ull S2[4][2];
#pragma unroll
        for (int i = 0; i < 4; i++) { S2[i][0] = 0ull; S2[i][1] = 0ull; }

#pragma unroll 4
        for (int d = 0; d < 64; d++) {
            float4 a4 = *(const float4*)(Qs + d * QP + 4 * ty);   // LDS.128 bcast
            ull ad0 = f2dup(a4.x), ad1 = f2dup(a4.y), ad2 = f2dup(a4.z), ad3 = f2dup(a4.w);
            float4 k4 = *(const float4*)(Ks + d * QP + 4 * tx);   // LDS.128
            ull k01 = f2pk(k4.x, k4.y);
            ull k23 = f2pk(k4.z, k4.w);
            S2[0][0] = f2fma(ad0, k01, S2[0][0]);
            S2[0][1] = f2fma(ad0, k23, S2[0][1]);
            S2[1][0] = f2fma(ad1, k01, S2[1][0]);
            S2[1][1] = f2fma(ad1, k23, S2[1][1]);
            S2[2][0] = f2fma(ad2, k01, S2[2][0]);
            S2[2][1] = f2fma(ad2, k23, S2[2][1]);
            S2[3][0] = f2fma(ad3, k01, S2[3][0]);
            S2[3][1] = f2fma(ad3, k23, S2[3][1]);
        }

        // online softmax; p kept in registers: P4[i][j] = p for row 4ty+i,
        // col 4tx+j
        float P4[4][4];
#pragma unroll
        for (int i = 0; i < 4; i++) {
            float s0v, s1v, s2v, s3v;
            f2upk(S2[i][0], s0v, s1v);
            f2upk(S2[i][1], s2v, s3v);
            float rm = fmaxf(fmaxf(s0v, s1v), fmaxf(s2v, s3v));
#pragma unroll
            for (int off = 8; off >= 1; off >>= 1)
                rm = fmaxf(rm, __shfl_xor_sync(0xffffffffu, rm, off));
            float mn = fmaxf(m[i], rm);
            float corr = __expf(m[i] - mn);
            m[i] = mn;
            float p0 = __expf(s0v - mn), p1 = __expf(s1v - mn);
            float p2 = __expf(s2v - mn), p3 = __expf(s3v - mn);
            float rs = (p0 + p1) + (p2 + p3);
#pragma unroll
            for (int off = 8; off >= 1; off >>= 1)
                rs += __shfl_xor_sync(0xffffffffu, rs, off);
            l[i] = l[i] * corr + rs;
            ull cd = f2dup(corr);
#pragma unroll
            for (int j = 0; j < 4; j++) O2[i][j] = f2mul(O2[i][j], cd);
            P4[i][0] = p0; P4[i][1] = p1; P4[i][2] = p2; P4[i][3] = p3;
        }
        // no CTA sync needed here: GEMM2 consumes P via intra-warp shuffles

        // GEMM2: O[64r x 128c] += P[64r x 64s] @ V[64s x 128c]
        // O cols per thread: group0 = 4tx+{0..3}, group1 = 64+4tx+{0..3}
        // p[s][4ty+i] comes from lane (halfbase | s>>2), register s&3
#pragma unroll 4
        for (int s4 = 0; s4 < 16; s4++) {
            int src = halfbase | s4;
#pragma unroll
            for (int j = 0; j < 4; j++) {
                int s = 4 * s4 + j;
                ull pd0 = f2dup(__shfl_sync(0xffffffffu, P4[0][j], src));
                ull pd1 = f2dup(__shfl_sync(0xffffffffu, P4[1][j], src));
                ull pd2 = f2dup(__shfl_sync(0xffffffffu, P4[2][j], src));
                ull pd3 = f2dup(__shfl_sync(0xffffffffu, P4[3][j], src));
                float4 va = *(const float4*)(Vs + s * VP + 4 * tx);        // LDS.128
                float4 vb = *(const float4*)(Vs + s * VP + 64 + 4 * tx);   // LDS.128
                ull va01 = f2pk(va.x, va.y);
                ull va23 = f2pk(va.z, va.w);
                ull vb01 = f2pk(vb.x, vb.y);
                ull vb23 = f2pk(vb.z, vb.w);
                O2[0][0] = f2fma(pd0, va01, O2[0][0]);
                O2[0][1] = f2fma(pd0, va23, O2[0][1]);
                O2[0][2] = f2fma(pd0, vb01, O2[0][2]);
                O2[0][3] = f2fma(pd0, vb23, O2[0][3]);
                O2[1][0] = f2fma(pd1, va01, O2[1][0]);
                O2[1][1] = f2fma(pd1, va23, O2[1][1]);
                O2[1][2] = f2fma(pd1, vb01, O2[1][2]);
                O2[1][3] = f2fma(pd1, vb23, O2[1][3]);
                O2[2][0] = f2fma(pd2, va01, O2[2][0]);
                O2[2][1] = f2fma(pd2, va23, O2[2][1]);
                O2[2][2] = f2fma(pd2, vb01, O2[2][2]);
                O2[2][3] = f2fma(pd2, vb23, O2[2][3]);
                O2[3][0] = f2fma(pd3, va01, O2[3][0]);
                O2[3][1] = f2fma(pd3, va23, O2[3][1]);
                O2[3][2] = f2fma(pd3, vb01, O2[3][2]);
                O2[3][3] = f2fma(pd3, vb23, O2[3][3]);
            }
        }
        __syncthreads();   // protects Ks/Vs reuse next iteration
    }

    // normalize + transpose through smem for coalesced global writes
    float* Os = sm;   // Os[c*65 + r]: 128*65 = 8320 floats, reuses Qs+Ks region
#pragma unroll
    for (int i = 0; i < 4; i++) {
        float inv = 1.f / l[i];
        int r = 4 * ty + i;
#pragma unroll
        for (int g = 0; g < 2; g++) {
            float c0, c1, c2, c3;
            f2upk(O2[i][2 * g],     c0, c1);
            f2upk(O2[i][2 * g + 1], c2, c3);
            int cb = 64 * g + 4 * tx;
            Os[(cb + 0) * 65 + r] = c0 * inv;
            Os[(cb + 1) * 65 + r] = c1 * inv;
            Os[(cb + 2) * 65 + r] = c2 * inv;
            Os[(cb + 3) * 65 + r] = c3 * inv;
        }
    }
    __syncthreads();

    const float* xb = x   + (size_t)(b * 512 + h * 128) * N_;
    float*       ob = out + (size_t)(b * 512 + h * 128) * N_;
    for (int idx = tid; idx < 128 * 64; idx += 256) {
        int r = idx & 63, c = idx >> 6;
        ob[(size_t)c * N_ + n0 + r] = Os[c * 65 + r] + xb[(size_t)c * N_ + n0 + r];
    }
}

// ---------------- launcher -------------------------------------------------
extern "C" void kernel_launch(void* const* d_in, const int* in_sizes, int n_in,
                              void* d_out, int out_size)
{
    const float* x = (const float*)d_in[0];

    fold_kernel<<<(OTOT * CIN + 255) / 256, 256>>>(
        (const float*)d_in[1],  (const float*)d_in[2],
        (const float*)d_in[3],  (const float*)d_in[4],
        (const float*)d_in[5],  (const float*)d_in[6],
        (const float*)d_in[7],  (const float*)d_in[8],
        (const float*)d_in[9],  (const float*)d_in[10],
        (const float*)d_in[11], (const float*)d_in[12],
        (const float*)d_in[13], (const float*)d_in[14],
        (const float*)d_in[15], (const float*)d_in[16],
        (const float*)d_in[17], (const float*)d_in[18]);

    pos_kernel<<<(HEADS_ * DH_ * N_ + 255) / 256, 256>>>(
        (const float*)d_in[19], (const float*)d_in[20]);

    qkv_gemm<<<dim3(N_ / 64, OTOT / 64, B_), 256>>>(x);

    cudaFuncSetAttribute(attn_kernel,
                         cudaFuncAttributeMaxDynamicSharedMemorySize,
                         ATTN_SMEM_BYTES);
    attn_kernel<<<dim3(N_ / 64, HEADS_, B_), 256, ATTN_SMEM_BYTES>>>(x, (float*)d_out);
}